// round 12
// baseline (speedup 1.0000x reference)
#include <cuda_runtime.h>
#include <cstdint>

// VQExpert, round 12. Three-kernel design:
//  precompute: T (cb->y table), M=Wp@Wd (fp64 acc), bz, packed g_Wd2/g_Wp2, zero flag counter
//  kernel1:   folded z + packed-key argmin with margin guard; flagged rows -> g_list
//  kernel2:   exact two-step recompute (R4 bit-exact order) of flagged rows only

typedef unsigned long long ull;
#define FULLMASK 0xffffffffu

constexpr int NROW   = 500000;
constexpr int WARPS  = 16;
constexpr int RPW    = 16;                       // fold rows per warp
constexpr int TILE   = WARPS * RPW;              // 256
constexpr int NTILES = (NROW + TILE - 1) / TILE; // 1954
constexpr float TH   = 6e-3f;

// kernel1 smem (floats)
constexpr int O_M2 = 0;           // 32x128 quad: [(k>>2)*128 + c*4 + (k&3)]
constexpr int O_CB = 4096;        // codebook quad: [(d>>2)*1024 + c*4 + (d&3)]
constexpr int O_CN = 12288;       // 256 code norms
constexpr int O_BZ = 12544;       // 32
constexpr int O_TS = 12576;       // 16 warps x (16 rows x 128) x stripes
constexpr int O_ZA = O_TS + WARPS * RPW * 128;   // 16 warps x (16 x 32) z
constexpr int SM1_FLOATS = O_ZA + WARPS * RPW * 32;   // 53536
constexpr int SM1_BYTES  = SM1_FLOATS * 4;            // 214,144 B

// kernel2 smem (floats)
constexpr int O2_WD2 = 0;         // 128x128 k-pair: [(k>>1)*256 + j*2 + (k&1)]
constexpr int O2_WP2 = 16384;     // 32x128 quad
constexpr int O2_CB  = 20480;     // codebook quad
constexpr int O2_CN  = 28672;
constexpr int O2_BD  = 28928;
constexpr int O2_BP  = 29056;
constexpr int O2_WS  = 29088;     // per-warp scratch: 128 h + 32 z
constexpr int SM2_FLOATS = O2_WS + 8 * 160;           // 30368
constexpr int SM2_BYTES  = SM2_FLOATS * 4;            // 121,472 B

__device__ float g_T[256 * 128];
__device__ float g_M[32 * 128];
__device__ float g_bz[32];
__device__ float g_Wd2[128 * 128];   // k-pair interleaved copy of Wd
__device__ float g_Wp2[32 * 128];    // quad-packed copy of Wp
__device__ int   g_nfb;
__device__ int   g_list[NROW];

__device__ __forceinline__ ull ffma2(ull a, ull b, ull c) {
    ull d;
    asm("fma.rn.f32x2 %0, %1, %2, %3;" : "=l"(d) : "l"(a), "l"(b), "l"(c));
    return d;
}
__device__ __forceinline__ float f2sum(ull v) {
    float a, b;
    asm("mov.b64 {%0, %1}, %2;" : "=f"(a), "=f"(b) : "l"(v));
    return a + b;
}
__device__ __forceinline__ void cpa16(uint32_t daddr, const void* g) {
    asm volatile("cp.async.ca.shared.global [%0], [%1], 16;" :: "r"(daddr), "l"(g));
}
__device__ __forceinline__ void cpa_commit() { asm volatile("cp.async.commit_group;"); }
__device__ __forceinline__ void cpa_wait0()  { asm volatile("cp.async.wait_group 0;"); }
__device__ __forceinline__ unsigned fkey(float s) {
    unsigned u = __float_as_uint(s);
    return u ^ ((u >> 31) ? 0xFFFFFFFFu : 0x80000000u);
}
__device__ __forceinline__ float kinv(unsigned k) {
    unsigned u = (k & 0x80000000u) ? (k ^ 0x80000000u) : ~k;
    return __uint_as_float(u);
}

// ---------------- prologue ----------------
__global__ void __launch_bounds__(128)
vq_precompute_kernel(const float* __restrict__ cb,
                     const float* __restrict__ Wd, const float* __restrict__ bd,
                     const float* __restrict__ Wp, const float* __restrict__ bp,
                     const float* __restrict__ Wo, const float* __restrict__ bo,
                     const float* __restrict__ Wu, const float* __restrict__ bu)
{
    __shared__ float v[128];
    const int i = threadIdx.x;
    const int c = blockIdx.x;
    if (c < 256) {
        float s = 0.f;
        #pragma unroll 8
        for (int d = 0; d < 32; d++) s = fmaf(cb[c * 32 + d], Wo[i * 32 + d], s);
        v[i] = s;
        __syncthreads();
        float t = 0.f, Bi = bu[i];
        #pragma unroll 8
        for (int j = 0; j < 128; j++) {
            t  = fmaf(v[j],  Wu[i * 128 + j], t);
            Bi = fmaf(bo[j], Wu[i * 128 + j], Bi);
        }
        g_T[c * 128 + i] = t + Bi;
    } else if (c < 288) {
        int zc = c - 256;
        double s = 0.0;
        for (int h = 0; h < 128; h++)
            s += (double)Wp[zc * 128 + h] * (double)Wd[h * 128 + i];
        g_M[zc * 128 + i] = (float)s;
    } else if (c == 288) {
        if (i < 32) {
            double s = (double)bp[i];
            for (int h = 0; h < 128; h++) s += (double)Wp[i * 128 + h] * (double)bd[h];
            g_bz[i] = (float)s;
        }
        if (i == 64) g_nfb = 0;
    } else if (c < 417) {
        int idx = (c - 289) * 128 + i;          // pack Wd -> k-pair interleave
        int j = idx >> 7, k = idx & 127;
        g_Wd2[(k >> 1) * 256 + j * 2 + (k & 1)] = Wd[idx];
    } else if (c < 449) {
        int idx = (c - 417) * 128 + i;          // pack Wp -> quad
        int cc = idx >> 7, k = idx & 127;
        g_Wp2[(k >> 2) * 128 + cc * 4 + (k & 3)] = Wp[idx];
    }
}

// ---------------- kernel1: folded fast path ----------------
__global__ void __launch_bounds__(512, 1)
vq_expert_kernel(const float* __restrict__ x,
                 const float* __restrict__ cb,
                 float* __restrict__ out)
{
    extern __shared__ float sm[];
    const int tid = threadIdx.x;

    for (int i = tid; i < 4096; i += 512) {
        int c = i >> 7, k = i & 127;
        sm[O_M2 + (k >> 2) * 128 + c * 4 + (k & 3)] = g_M[i];
    }
    for (int i = tid; i < 256 * 32; i += 512) {
        int c = i >> 5, d = i & 31;
        sm[O_CB + (d >> 2) * 1024 + c * 4 + (d & 3)] = cb[i];
    }
    for (int c = tid; c < 256; c += 512) {
        float s = 0.f;
        #pragma unroll 8
        for (int d = 0; d < 32; d++) { float v = cb[c * 32 + d]; s = fmaf(v, v, s); }
        sm[O_CN + c] = s;
    }
    if (tid < 32) sm[O_BZ + tid] = g_bz[tid];
    if (blockIdx.x == 0 && tid == 0)
        out[(size_t)NROW * 128 + NROW] = 0.0f;    // commit_loss == 0 exactly
    __syncthreads();

    const int wid  = tid >> 5;
    const int lane = tid & 31;
    float* myts = sm + O_TS + wid * (RPW * 128);
    float* myza = sm + O_ZA + wid * (RPW * 32);
    const float bzv = sm[O_BZ + lane];

    float* outY = out;
    float* outI = out + (size_t)NROW * 128;

    uint32_t sb = (uint32_t)__cvta_generic_to_shared(myts + 4 * lane);

    for (int tile = blockIdx.x; tile < NTILES; tile += gridDim.x) {
        const int row0 = tile * TILE + wid * RPW;
        if (row0 >= NROW) continue;
        const bool full = (row0 + RPW <= NROW);

        // stage x (16 rows)
        #pragma unroll
        for (int r = 0; r < RPW; r++)
            if (full || row0 + r < NROW)
                cpa16(sb + r * 512, x + (size_t)(row0 + r) * 128 + 4 * lane);
        cpa_commit();
        cpa_wait0();
        __syncwarp();

        // -------- folded z: z = x @ M^T + bz, lane = z-column, 16 rows --------
        {
            ull za[RPW];
            #pragma unroll
            for (int r = 0; r < RPW; r++) za[r] = 0ull;
            #pragma unroll 2
            for (int kq = 0; kq < 32; kq++) {
                ulonglong2 w = *(const ulonglong2*)(sm + O_M2 + kq * 128 + 4 * lane);
                #pragma unroll
                for (int r = 0; r < RPW; r++) {
                    ulonglong2 xk = *(const ulonglong2*)(myts + r * 128 + 4 * kq);
                    za[r] = ffma2(xk.x, w.x, za[r]);
                    za[r] = ffma2(xk.y, w.y, za[r]);
                }
            }
            __syncwarp();
            #pragma unroll
            for (int r = 0; r < RPW; r++)
                myza[r * 32 + lane] = bzv + f2sum(za[r]);
            __syncwarp();
        }

        // -------- argmin in two 8-row subtiles, packed score|idx keys --------
        #pragma unroll
        for (int s2 = 0; s2 < 2; s2++) {
            const float* zb = myza + s2 * 8 * 32;
            unsigned bk[8], sk[8];
            #pragma unroll
            for (int r = 0; r < 8; r++) { bk[r] = 0xFFFFFFFFu; sk[r] = 0xFFFFFFFFu; }

            #pragma unroll
            for (int half = 0; half < 2; half++) {
                ull da[8][4];
                #pragma unroll
                for (int r = 0; r < 8; r++)
                    #pragma unroll
                    for (int i = 0; i < 4; i++) da[r][i] = 0ull;

                #pragma unroll 2
                for (int dq = 0; dq < 8; dq++) {
                    ulonglong2 c2[4];
                    #pragma unroll
                    for (int i = 0; i < 4; i++)
                        c2[i] = *(const ulonglong2*)(sm + O_CB + dq * 1024
                                    + ((half * 4 + i) * 32 + lane) * 4);
                    #pragma unroll
                    for (int r = 0; r < 8; r++) {
                        ulonglong2 zq = *(const ulonglong2*)(zb + r * 32 + 4 * dq);
                        #pragma unroll
                        for (int i = 0; i < 4; i++) {
                            da[r][i] = ffma2(zq.x, c2[i].x, da[r][i]);
                            da[r][i] = ffma2(zq.y, c2[i].y, da[r][i]);
                        }
                    }
                }
                float cng[4];
                #pragma unroll
                for (int i = 0; i < 4; i++) cng[i] = sm[O_CN + (half * 4 + i) * 32 + lane];
                #pragma unroll
                for (int r = 0; r < 8; r++) {
                    #pragma unroll
                    for (int i = 0; i < 4; i++) {
                        float s = cng[i] - 2.0f * f2sum(da[r][i]);
                        unsigned pk = (fkey(s) & 0xFFFFFF00u)
                                    | (unsigned)(((half * 4 + i) << 5) | lane);
                        unsigned nb = umin(bk[r], pk);
                        sk[r] = umin(sk[r], umax(bk[r], pk));
                        bk[r] = nb;
                    }
                }
            }
            #pragma unroll
            for (int r = 0; r < 8; r++) {
                const int row = row0 + s2 * 8 + r;
                unsigned m1 = __reduce_min_sync(FULLMASK, bk[r]);
                unsigned cand = (bk[r] == m1) ? sk[r] : bk[r];
                unsigned m2 = __reduce_min_sync(FULLMASK, cand);
                int idx = (int)(m1 & 0xFFu);
                if (row < NROW) {
                    // flag boundary rows for exact recompute in kernel2
                    float margin = kinv(m2 & 0xFFFFFF00u) - kinv(m1 & 0xFFFFFF00u);
                    if (lane == 0 && !(margin >= TH)) {
                        int pos = atomicAdd(&g_nfb, 1);
                        g_list[pos] = row;
                    }
                    float4 t = ((const float4*)(g_T + idx * 128))[lane];
                    float4 y;
                    y.x = fminf(fmaxf(t.x, -1.0f), 1.0f);
                    y.y = fminf(fmaxf(t.y, -1.0f), 1.0f);
                    y.z = fminf(fmaxf(t.z, -1.0f), 1.0f);
                    y.w = fminf(fmaxf(t.w, -1.0f), 1.0f);
                    ((float4*)(outY + (size_t)row * 128))[lane] = y;
                    if (lane == 0) outI[row] = (float)idx;
                }
            }
        }
        __syncwarp();
    }
}

// ---------------- kernel2: exact recompute of flagged rows ----------------
__global__ void __launch_bounds__(256, 1)
vq_exact_kernel(const float* __restrict__ x,
                const float* __restrict__ cb,
                const float* __restrict__ bd, const float* __restrict__ bp,
                float* __restrict__ out)
{
    extern __shared__ float sm[];
    const int tid = threadIdx.x;

    for (int i = tid; i < 128 * 128; i += 256) sm[O2_WD2 + i] = g_Wd2[i];
    for (int i = tid; i < 4096; i += 256)      sm[O2_WP2 + i] = g_Wp2[i];
    for (int i = tid; i < 256 * 32; i += 256) {
        int c = i >> 5, d = i & 31;
        sm[O2_CB + (d >> 2) * 1024 + c * 4 + (d & 3)] = cb[i];
    }
    if (tid < 256) {
        float s = 0.f;
        #pragma unroll 8
        for (int d = 0; d < 32; d++) { float v = cb[tid * 32 + d]; s = fmaf(v, v, s); }
        sm[O2_CN + tid] = s;
    }
    if (tid < 128) sm[O2_BD + tid] = bd[tid];
    if (tid < 32)  sm[O2_BP + tid] = bp[tid];
    __syncthreads();

    const int wid  = tid >> 5;
    const int lane = tid & 31;
    float* hs   = sm + O2_WS + wid * 160;
    float* zrow = hs + 128;

    const float2 bd0 = *(const float2*)(sm + O2_BD + 2 * lane);
    const float2 bd1 = *(const float2*)(sm + O2_BD + 64 + 2 * lane);
    const float  bpv = sm[O2_BP + lane];

    float* outY = out;
    float* outI = out + (size_t)NROW * 128;

    const int n = g_nfb;
    const int gw = blockIdx.x * 8 + wid;
    const int nw = gridDim.x * 8;

    for (int i = gw; i < n; i += nw) {
        const int row = g_list[i];
        const float* xrow = x + (size_t)row * 128;

        // phase A (bit-identical order to the R4-validated path)
        ull a0 = 0, a1 = 0, a2 = 0, a3 = 0;
        for (int pp = 0; pp < 32; pp++) {
            const float* b0 = sm + O2_WD2 + (2 * pp) * 256;
            const float* b1 = b0 + 256;
            ulonglong2 wa0 = *(const ulonglong2*)(b0 + 4 * lane);
            ulonglong2 wb0 = *(const ulonglong2*)(b0 + 128 + 4 * lane);
            ulonglong2 wa1 = *(const ulonglong2*)(b1 + 4 * lane);
            ulonglong2 wb1 = *(const ulonglong2*)(b1 + 128 + 4 * lane);
            ulonglong2 xv  = *(const ulonglong2*)(xrow + 4 * pp);
            a0 = ffma2(xv.x, wa0.x, a0); a1 = ffma2(xv.x, wa0.y, a1);
            a2 = ffma2(xv.x, wb0.x, a2); a3 = ffma2(xv.x, wb0.y, a3);
            a0 = ffma2(xv.y, wa1.x, a0); a1 = ffma2(xv.y, wa1.y, a1);
            a2 = ffma2(xv.y, wb1.x, a2); a3 = ffma2(xv.y, wb1.y, a3);
        }
        __syncwarp();
        hs[2 * lane]          = bd0.x + f2sum(a0);
        hs[2 * lane + 1]      = bd0.y + f2sum(a1);
        hs[64 + 2 * lane]     = bd1.x + f2sum(a2);
        hs[64 + 2 * lane + 1] = bd1.y + f2sum(a3);
        __syncwarp();

        // phase B
        ull zacc = 0;
        for (int kq = 0; kq < 32; kq++) {
            ulonglong2 w  = *(const ulonglong2*)(sm + O2_WP2 + kq * 128 + 4 * lane);
            ulonglong2 h2 = *(const ulonglong2*)(hs + 4 * kq);
            zacc = ffma2(h2.x, w.x, zacc);
            zacc = ffma2(h2.y, w.y, zacc);
        }
        __syncwarp();
        zrow[lane] = bpv + f2sum(zacc);
        __syncwarp();

        // phase C: exact argmin
        ull dd[8];
        #pragma unroll
        for (int g = 0; g < 8; g++) dd[g] = 0ull;
        for (int dq = 0; dq < 8; dq++) {
            ulonglong2 zq = *(const ulonglong2*)(zrow + 4 * dq);
            #pragma unroll
            for (int g = 0; g < 8; g++) {
                ulonglong2 c2 = *(const ulonglong2*)(sm + O2_CB + dq * 1024 + (g * 32 + lane) * 4);
                dd[g] = ffma2(zq.x, c2.x, dd[g]);
                dd[g] = ffma2(zq.y, c2.y, dd[g]);
            }
        }
        unsigned bk = 0xFFFFFFFFu, bi = 0;
        #pragma unroll
        for (int g = 0; g < 8; g++) {
            float s = sm[O2_CN + g * 32 + lane] - 2.0f * f2sum(dd[g]);
            unsigned k = fkey(s);
            if (k < bk) { bk = k; bi = (unsigned)((g << 5) | lane); }
        }
        unsigned m = __reduce_min_sync(FULLMASK, bk);
        unsigned cand = (bk == m) ? bi : 0xFFFFFFFFu;
        int idx = (int)__reduce_min_sync(FULLMASK, cand);

        // overwrite y + idx
        float4 t = ((const float4*)(g_T + idx * 128))[lane];
        float4 y;
        y.x = fminf(fmaxf(t.x, -1.0f), 1.0f);
        y.y = fminf(fmaxf(t.y, -1.0f), 1.0f);
        y.z = fminf(fmaxf(t.z, -1.0f), 1.0f);
        y.w = fminf(fmaxf(t.w, -1.0f), 1.0f);
        ((float4*)(outY + (size_t)row * 128))[lane] = y;
        if (lane == 0) outI[row] = (float)idx;
    }
}

extern "C" void kernel_launch(void* const* d_in, const int* in_sizes, int n_in,
                              void* d_out, int out_size)
{
    const float* x  = (const float*)d_in[0];
    const float* Wd = (const float*)d_in[1];
    const float* bd = (const float*)d_in[2];
    const float* Wp = (const float*)d_in[3];
    const float* bp = (const float*)d_in[4];
    const float* cb = (const float*)d_in[5];
    const float* Wo = (const float*)d_in[6];
    const float* bo = (const float*)d_in[7];
    const float* Wu = (const float*)d_in[8];
    const float* bu = (const float*)d_in[9];
    float* out = (float*)d_out;

    cudaFuncSetAttribute(vq_expert_kernel,
                         cudaFuncAttributeMaxDynamicSharedMemorySize, SM1_BYTES);
    cudaFuncSetAttribute(vq_exact_kernel,
                         cudaFuncAttributeMaxDynamicSharedMemorySize, SM2_BYTES);

    vq_precompute_kernel<<<449, 128>>>(cb, Wd, bd, Wp, bp, Wo, bo, Wu, bu);
    vq_expert_kernel<<<148, 512, SM1_BYTES>>>(x, cb, out);
    vq_exact_kernel<<<148, 256, SM2_BYTES>>>(x, cb, bd, bp, out);
}

// round 13
// speedup vs baseline: 1.1370x; 1.1370x over previous
#include <cuda_runtime.h>
#include <cstdint>

// VQExpert fused kernel, round 13 = R11 frame (431us: folded z + inline margin-
// guarded exact fallback) + R12-validated packed score|idx argmin keys + cn in
// registers. No kernel2, no extra precompute blocks.

typedef unsigned long long ull;
#define FULLMASK 0xffffffffu

constexpr int NROW   = 500000;
constexpr int WARPS  = 16;
constexpr int RPW    = 8;
constexpr int TILE   = WARPS * RPW;              // 128
constexpr int NTILES = (NROW + TILE - 1) / TILE; // 3907
constexpr float TH   = 6e-3f;

// smem layout (floats)
constexpr int O_WD2 = 0;          // 128x128 k-pair: [(k>>1)*256 + j*2 + (k&1)]  (exact path)
constexpr int O_M2  = 16384;      // 32x128 quad: [(k>>2)*128 + c*4 + (k&3)]
constexpr int O_WP2 = 20480;      // 32x128 quad
constexpr int O_CB  = 24576;      // codebook quad: [(d>>2)*1024 + c*4 + (d&3)]
constexpr int O_CN  = 32768;      // 256 code norms
constexpr int O_BD  = 33024;
constexpr int O_BP  = 33152;
constexpr int O_BZ  = 33184;
constexpr int O_TS  = 33216;                      // 16 warps x (8 rows x 128)
constexpr int O_ZA  = O_TS + WARPS * RPW * 128;   // 16 warps x (8 x 32)
constexpr int O_HS  = O_ZA + WARPS * RPW * 32;    // 16 warps x 128 scratch h
constexpr int SMEM_FLOATS = O_HS + WARPS * 128;   // 55744
constexpr int SMEM_BYTES  = SMEM_FLOATS * 4;      // 222,976 B

__device__ float g_T[256 * 128];   // fused codebook->output table (bias folded)
__device__ float g_M[32 * 128];    // fused x->z projection (fp64-accumulated)
__device__ float g_bz[32];

__device__ __forceinline__ ull ffma2(ull a, ull b, ull c) {
    ull d;
    asm("fma.rn.f32x2 %0, %1, %2, %3;" : "=l"(d) : "l"(a), "l"(b), "l"(c));
    return d;
}
__device__ __forceinline__ float f2sum(ull v) {
    float a, b;
    asm("mov.b64 {%0, %1}, %2;" : "=f"(a), "=f"(b) : "l"(v));
    return a + b;
}
__device__ __forceinline__ void cpa16(uint32_t daddr, const void* g) {
    asm volatile("cp.async.ca.shared.global [%0], [%1], 16;" :: "r"(daddr), "l"(g));
}
__device__ __forceinline__ void cpa_commit() { asm volatile("cp.async.commit_group;"); }
__device__ __forceinline__ void cpa_wait0()  { asm volatile("cp.async.wait_group 0;"); }
__device__ __forceinline__ unsigned fkey(float s) {
    unsigned u = __float_as_uint(s);
    return u ^ ((u >> 31) ? 0xFFFFFFFFu : 0x80000000u);
}
__device__ __forceinline__ float kinv(unsigned k) {
    unsigned u = (k & 0x80000000u) ? (k ^ 0x80000000u) : ~k;
    return __uint_as_float(u);
}

// ---------------- prologue ----------------
__global__ void __launch_bounds__(128)
vq_precompute_kernel(const float* __restrict__ cb,
                     const float* __restrict__ Wd, const float* __restrict__ bd,
                     const float* __restrict__ Wp, const float* __restrict__ bp,
                     const float* __restrict__ Wo, const float* __restrict__ bo,
                     const float* __restrict__ Wu, const float* __restrict__ bu)
{
    __shared__ float v[128];
    const int i = threadIdx.x;
    const int c = blockIdx.x;
    if (c < 256) {
        float s = 0.f;
        #pragma unroll 8
        for (int d = 0; d < 32; d++) s = fmaf(cb[c * 32 + d], Wo[i * 32 + d], s);
        v[i] = s;
        __syncthreads();
        float t = 0.f, Bi = bu[i];
        #pragma unroll 8
        for (int j = 0; j < 128; j++) {
            t  = fmaf(v[j],  Wu[i * 128 + j], t);
            Bi = fmaf(bo[j], Wu[i * 128 + j], Bi);
        }
        g_T[c * 128 + i] = t + Bi;
    } else if (c < 288) {
        int zc = c - 256;              // M[zc][i] in double for tight folded error
        double s = 0.0;
        for (int h = 0; h < 128; h++)
            s += (double)Wp[zc * 128 + h] * (double)Wd[h * 128 + i];
        g_M[zc * 128 + i] = (float)s;
    } else if (i < 32) {
        double s = (double)bp[i];
        for (int h = 0; h < 128; h++) s += (double)Wp[i * 128 + h] * (double)bd[h];
        g_bz[i] = (float)s;
    }
}

// exact two-step recompute for one row (bit-identical order to the R4 path).
__device__ __noinline__ int exact_row(const float* sm, const float* xrow,
                                      float* hs, float* zrow, int lane,
                                      float2 bd0, float2 bd1, float bpv)
{
    ull a0 = 0, a1 = 0, a2 = 0, a3 = 0;
    for (int pp = 0; pp < 32; pp++) {
        const float* b0 = sm + O_WD2 + (2 * pp) * 256;
        const float* b1 = b0 + 256;
        ulonglong2 wa0 = *(const ulonglong2*)(b0 + 4 * lane);
        ulonglong2 wb0 = *(const ulonglong2*)(b0 + 128 + 4 * lane);
        ulonglong2 wa1 = *(const ulonglong2*)(b1 + 4 * lane);
        ulonglong2 wb1 = *(const ulonglong2*)(b1 + 128 + 4 * lane);
        ulonglong2 xv  = *(const ulonglong2*)(xrow + 4 * pp);
        a0 = ffma2(xv.x, wa0.x, a0); a1 = ffma2(xv.x, wa0.y, a1);
        a2 = ffma2(xv.x, wb0.x, a2); a3 = ffma2(xv.x, wb0.y, a3);
        a0 = ffma2(xv.y, wa1.x, a0); a1 = ffma2(xv.y, wa1.y, a1);
        a2 = ffma2(xv.y, wb1.x, a2); a3 = ffma2(xv.y, wb1.y, a3);
    }
    __syncwarp();
    hs[2 * lane]          = bd0.x + f2sum(a0);
    hs[2 * lane + 1]      = bd0.y + f2sum(a1);
    hs[64 + 2 * lane]     = bd1.x + f2sum(a2);
    hs[64 + 2 * lane + 1] = bd1.y + f2sum(a3);
    __syncwarp();
    ull zacc = 0;
    for (int kq = 0; kq < 32; kq++) {
        ulonglong2 w  = *(const ulonglong2*)(sm + O_WP2 + kq * 128 + 4 * lane);
        ulonglong2 h2 = *(const ulonglong2*)(hs + 4 * kq);
        zacc = ffma2(h2.x, w.x, zacc);
        zacc = ffma2(h2.y, w.y, zacc);
    }
    __syncwarp();
    zrow[lane] = bpv + f2sum(zacc);
    __syncwarp();
    ull dd[8];
    #pragma unroll
    for (int g = 0; g < 8; g++) dd[g] = 0ull;
    for (int dq = 0; dq < 8; dq++) {
        ulonglong2 zq = *(const ulonglong2*)(zrow + 4 * dq);
        #pragma unroll
        for (int g = 0; g < 8; g++) {
            ulonglong2 c2 = *(const ulonglong2*)(sm + O_CB + dq * 1024 + (g * 32 + lane) * 4);
            dd[g] = ffma2(zq.x, c2.x, dd[g]);
            dd[g] = ffma2(zq.y, c2.y, dd[g]);
        }
    }
    unsigned bk = 0xFFFFFFFFu, bi = 0;
    #pragma unroll
    for (int g = 0; g < 8; g++) {
        float s = sm[O_CN + g * 32 + lane] - 2.0f * f2sum(dd[g]);
        unsigned k = fkey(s);
        if (k < bk) { bk = k; bi = (unsigned)((g << 5) | lane); }
    }
    unsigned m = __reduce_min_sync(FULLMASK, bk);
    unsigned cand = (bk == m) ? bi : 0xFFFFFFFFu;
    return (int)__reduce_min_sync(FULLMASK, cand);
}

// ---------------- main kernel ----------------
__global__ void __launch_bounds__(512, 1)
vq_expert_kernel(const float* __restrict__ x,
                 const float* __restrict__ Wd, const float* __restrict__ bd,
                 const float* __restrict__ Wp, const float* __restrict__ bp,
                 const float* __restrict__ cb,
                 float* __restrict__ out)
{
    extern __shared__ float sm[];
    const int tid = threadIdx.x;

    for (int i = tid; i < 128 * 128; i += 512) {
        int j = i >> 7, k = i & 127;
        sm[O_WD2 + (k >> 1) * 256 + j * 2 + (k & 1)] = Wd[i];
    }
    for (int i = tid; i < 4096; i += 512) {
        int c = i >> 7, k = i & 127;
        sm[O_M2  + (k >> 2) * 128 + c * 4 + (k & 3)] = g_M[i];
        sm[O_WP2 + (k >> 2) * 128 + c * 4 + (k & 3)] = Wp[i];
    }
    for (int i = tid; i < 256 * 32; i += 512) {
        int c = i >> 5, d = i & 31;
        sm[O_CB + (d >> 2) * 1024 + c * 4 + (d & 3)] = cb[i];
    }
    for (int c = tid; c < 256; c += 512) {
        float s = 0.f;
        #pragma unroll 8
        for (int d = 0; d < 32; d++) { float v = cb[c * 32 + d]; s = fmaf(v, v, s); }
        sm[O_CN + c] = s;
    }
    if (tid < 128) sm[O_BD + tid] = bd[tid];
    else if (tid < 160) sm[O_BP + tid - 128] = bp[tid - 128];
    else if (tid < 192) sm[O_BZ + tid - 160] = g_bz[tid - 160];
    if (blockIdx.x == 0 && tid == 0)
        out[(size_t)NROW * 128 + NROW] = 0.0f;    // commit_loss == 0 exactly
    __syncthreads();

    const int wid  = tid >> 5;
    const int lane = tid & 31;
    float* myts = sm + O_TS + wid * (RPW * 128);
    float* myza = sm + O_ZA + wid * (RPW * 32);
    float* myhs = sm + O_HS + wid * 128;

    const float2 bd0 = *(const float2*)(sm + O_BD + 2 * lane);
    const float2 bd1 = *(const float2*)(sm + O_BD + 64 + 2 * lane);
    const float  bpv = sm[O_BP + lane];
    const float  bzv = sm[O_BZ + lane];
    float cnr[8];
    #pragma unroll
    for (int g = 0; g < 8; g++) cnr[g] = sm[O_CN + g * 32 + lane];

    float* outY = out;
    float* outI = out + (size_t)NROW * 128;

    uint32_t sb = (uint32_t)__cvta_generic_to_shared(myts + 4 * lane);

    for (int tile = blockIdx.x; tile < NTILES; tile += gridDim.x) {
        const int row0 = tile * TILE + wid * RPW;
        if (row0 >= NROW) continue;
        const bool full = (row0 + RPW <= NROW);

        // stage x (stays live through the whole tile for the exact fallback)
        #pragma unroll
        for (int r = 0; r < RPW; r++)
            if (full || row0 + r < NROW)
                cpa16(sb + r * 512, x + (size_t)(row0 + r) * 128 + 4 * lane);
        cpa_commit();
        cpa_wait0();
        __syncwarp();

        // -------- folded z: z_f = x @ M^T + bz, lane = z-column --------
        ull za[RPW];
        #pragma unroll
        for (int r = 0; r < RPW; r++) za[r] = 0ull;
        #pragma unroll 4
        for (int kq = 0; kq < 32; kq++) {
            ulonglong2 w = *(const ulonglong2*)(sm + O_M2 + kq * 128 + 4 * lane);
            #pragma unroll
            for (int r = 0; r < RPW; r++) {
                ulonglong2 xk = *(const ulonglong2*)(myts + r * 128 + 4 * kq);
                za[r] = ffma2(xk.x, w.x, za[r]);
                za[r] = ffma2(xk.y, w.y, za[r]);
            }
        }
        __syncwarp();
        #pragma unroll
        for (int r = 0; r < RPW; r++)
            myza[r * 32 + lane] = bzv + f2sum(za[r]);
        __syncwarp();

        // -------- folded argmin, packed score|idx keys (R12-validated) --------
        unsigned bk[RPW], sk[RPW];
        #pragma unroll
        for (int r = 0; r < RPW; r++) { bk[r] = 0xFFFFFFFFu; sk[r] = 0xFFFFFFFFu; }

        #pragma unroll
        for (int half = 0; half < 2; half++) {
            ull da[RPW][4];
            #pragma unroll
            for (int r = 0; r < RPW; r++)
                #pragma unroll
                for (int i = 0; i < 4; i++) da[r][i] = 0ull;

            #pragma unroll 2
            for (int dq = 0; dq < 8; dq++) {
                ulonglong2 c2[4];
                #pragma unroll
                for (int i = 0; i < 4; i++)
                    c2[i] = *(const ulonglong2*)(sm + O_CB + dq * 1024
                                + ((half * 4 + i) * 32 + lane) * 4);
                #pragma unroll
                for (int r = 0; r < RPW; r++) {
                    ulonglong2 zq = *(const ulonglong2*)(myza + r * 32 + 4 * dq);
                    #pragma unroll
                    for (int i = 0; i < 4; i++) {
                        da[r][i] = ffma2(zq.x, c2[i].x, da[r][i]);
                        da[r][i] = ffma2(zq.y, c2[i].y, da[r][i]);
                    }
                }
            }
            #pragma unroll
            for (int r = 0; r < RPW; r++) {
                #pragma unroll
                for (int i = 0; i < 4; i++) {
                    int g = half * 4 + i;
                    float s = cnr[g] - 2.0f * f2sum(da[r][i]);
                    unsigned pk = (fkey(s) & 0xFFFFFF00u)
                                | (unsigned)((g << 5) | lane);
                    unsigned nb = umin(bk[r], pk);
                    sk[r] = umin(sk[r], umax(bk[r], pk));
                    bk[r] = nb;
                }
            }
        }

        int bc[RPW];
        #pragma unroll
        for (int r = 0; r < RPW; r++) {
            unsigned m1 = __reduce_min_sync(FULLMASK, bk[r]);
            unsigned cand = (bk[r] == m1) ? sk[r] : bk[r];
            unsigned m2 = __reduce_min_sync(FULLMASK, cand);
            int idx = (int)(m1 & 0xFFu);
            float margin = kinv(m2 & 0xFFFFFF00u) - kinv(m1 & 0xFFFFFF00u);
            if (!(margin >= TH) && (full || row0 + r < NROW)) {
                // boundary row: exact two-step recompute (R4-validated path)
                idx = exact_row(sm, myts + r * 128, myhs, myza + r * 32,
                                lane, bd0, bd1, bpv);
            }
            bc[r] = idx;
        }

        // -------- epilogue: y = clamp(T[bc], -1, 1) --------
        #pragma unroll
        for (int r = 0; r < RPW; r++) {
            if (full || row0 + r < NROW) {
                float4 t = ((const float4*)(g_T + bc[r] * 128))[lane];
                float4 y;
                y.x = fminf(fmaxf(t.x, -1.0f), 1.0f);
                y.y = fminf(fmaxf(t.y, -1.0f), 1.0f);
                y.z = fminf(fmaxf(t.z, -1.0f), 1.0f);
                y.w = fminf(fmaxf(t.w, -1.0f), 1.0f);
                ((float4*)(outY + (size_t)(row0 + r) * 128))[lane] = y;
            }
        }
        if (lane == 0) {
            #pragma unroll
            for (int r = 0; r < RPW; r++)
                if (row0 + r < NROW) outI[row0 + r] = (float)bc[r];
        }
        __syncwarp();
    }
}

extern "C" void kernel_launch(void* const* d_in, const int* in_sizes, int n_in,
                              void* d_out, int out_size)
{
    const float* x  = (const float*)d_in[0];
    const float* Wd = (const float*)d_in[1];
    const float* bd = (const float*)d_in[2];
    const float* Wp = (const float*)d_in[3];
    const float* bp = (const float*)d_in[4];
    const float* cb = (const float*)d_in[5];
    const float* Wo = (const float*)d_in[6];
    const float* bo = (const float*)d_in[7];
    const float* Wu = (const float*)d_in[8];
    const float* bu = (const float*)d_in[9];
    float* out = (float*)d_out;

    cudaFuncSetAttribute(vq_expert_kernel,
                         cudaFuncAttributeMaxDynamicSharedMemorySize, SMEM_BYTES);

    vq_precompute_kernel<<<289, 128>>>(cb, Wd, bd, Wp, bp, Wo, bo, Wu, bu);
    vq_expert_kernel<<<148, 512, SMEM_BYTES>>>(x, Wd, bd, Wp, bp, cb, out);
}